// round 1
// baseline (speedup 1.0000x reference)
#include <cuda_runtime.h>

// ---------------------------------------------------------------------------
// LinearAttention:  b=16, dim=384, n=64*64=4096, heads=4, ch=96
//  1. xn = chanLN(x) * prenorm_g
//  2. qkv = Wqkv @ xn   (per-position 1x1 conv == batched GEMM)
//  3. q = softmax over ch (96) * scale ; k = softmax over n (4096)
//  4. ctx[d,e] = sum_n k[d,n] v[e,n]           (per b,h : 96x96)
//  5. FUSION:  Wout @ (ctx^T @ q)  ==  W2 @ q  with
//              W2[o, h*96+d] = sum_e Wout[o, h*96+e] * ctx[b,h,d,e]
//  6. out2 = W2 @ q + bout ; out = chanLN(out2)*outnorm_g + xn
// ---------------------------------------------------------------------------

#define BATCH 16
#define CDIM  384
#define NPOS  4096
#define HEADS 4
#define CH    96
#define OC    1152          // 3*CDIM
#define QSCALE 0.1020620726159658f   // 96^-0.5

// scratch (device globals: allocation-free rule)
static __device__ float g_xn  [BATCH * CDIM * NPOS];   // 100 MB
static __device__ float g_qkv [BATCH * OC   * NPOS];   // 302 MB
static __device__ float g_ctx [BATCH * HEADS * CH * CH];
static __device__ float g_w2  [BATCH * CDIM * CDIM];
static __device__ float g_out2[BATCH * CDIM * NPOS];   // 100 MB

// ---------------------------------------------------------------- prenorm LN
__global__ void ln_pre_kernel(const float* __restrict__ x,
                              const float* __restrict__ g)
{
    int n = blockIdx.x * blockDim.x + threadIdx.x;   // 0..4095
    int b = blockIdx.y;
    const float* xp = x + (size_t)b * CDIM * NPOS + n;
    float s = 0.f, ss = 0.f;
#pragma unroll 8
    for (int c = 0; c < CDIM; c++) {
        float v = xp[(size_t)c * NPOS];
        s += v; ss += v * v;
    }
    float mean = s * (1.f / CDIM);
    float var  = ss * (1.f / CDIM) - mean * mean;
    float inv  = rsqrtf(var + 1e-5f);
    float* op = g_xn + (size_t)b * CDIM * NPOS + n;
#pragma unroll 8
    for (int c = 0; c < CDIM; c++)
        op[(size_t)c * NPOS] = (xp[(size_t)c * NPOS] - mean) * inv * g[c];
}

// ------------------------------------------------------- batched SGEMM 128x128x8
// C[bz] (MxN) = A[bz] (MxK, row-major) * B[bz] (KxN, row-major)  (+ bias[m])
template<bool BIAS>
__global__ __launch_bounds__(256, 2)
void sgemm_kernel(const float* __restrict__ A,  long long strideA,
                  const float* __restrict__ Bm, long long strideB,
                  float* __restrict__ Cm,       long long strideC,
                  const float* __restrict__ bias,
                  int M, int N, int K)
{
    __shared__ float As[8][132];   // padded: conflict-free transposed stores
    __shared__ float Bs[8][128];

    int bz = blockIdx.z;
    const float* Ab = A  + strideA * bz;
    const float* Bb = Bm + strideB * bz;
    float*       Cb = Cm + strideC * bz;

    int m0 = blockIdx.y * 128;
    int n0 = blockIdx.x * 128;
    int tid = threadIdx.x;

    int arow = tid >> 1;            // 0..127
    int acol = (tid & 1) * 4;       // 0 / 4
    int brow = tid >> 5;            // 0..7
    int bcol = (tid & 31) * 4;      // 0..124
    int mb = (tid >> 4) * 8;        // 0..120
    int nb = (tid & 15) * 8;

    float acc[8][8];
#pragma unroll
    for (int i = 0; i < 8; i++)
#pragma unroll
        for (int j = 0; j < 8; j++) acc[i][j] = 0.f;

    for (int k0 = 0; k0 < K; k0 += 8) {
        float4 av = *(const float4*)(Ab + (size_t)(m0 + arow) * K + k0 + acol);
        float4 bv = *(const float4*)(Bb + (size_t)(k0 + brow) * N + n0 + bcol);
        __syncthreads();
        As[acol + 0][arow] = av.x;
        As[acol + 1][arow] = av.y;
        As[acol + 2][arow] = av.z;
        As[acol + 3][arow] = av.w;
        *(float4*)&Bs[brow][bcol] = bv;
        __syncthreads();
#pragma unroll
        for (int kk = 0; kk < 8; kk++) {
            float a[8], bvr[8];
            *(float4*)&a[0]   = *(const float4*)&As[kk][mb];
            *(float4*)&a[4]   = *(const float4*)&As[kk][mb + 4];
            *(float4*)&bvr[0] = *(const float4*)&Bs[kk][nb];
            *(float4*)&bvr[4] = *(const float4*)&Bs[kk][nb + 4];
#pragma unroll
            for (int i = 0; i < 8; i++)
#pragma unroll
                for (int j = 0; j < 8; j++)
                    acc[i][j] = fmaf(a[i], bvr[j], acc[i][j]);
        }
    }

#pragma unroll
    for (int i = 0; i < 8; i++) {
        int m = m0 + mb + i;
        float bi = BIAS ? bias[m] : 0.f;
        float* cp = Cb + (size_t)m * N + n0 + nb;
        float4 r0 = make_float4(acc[i][0] + bi, acc[i][1] + bi, acc[i][2] + bi, acc[i][3] + bi);
        float4 r1 = make_float4(acc[i][4] + bi, acc[i][5] + bi, acc[i][6] + bi, acc[i][7] + bi);
        *(float4*)(cp)     = r0;
        *(float4*)(cp + 4) = r1;
    }
}

// -------------------------------------------- q softmax over 96 channels, *scale
__global__ void softmax_q_kernel()
{
    __shared__ float sq[CH][128];        // 48 KB
    int n0 = blockIdx.x * 128;
    int h  = blockIdx.y;
    int b  = blockIdx.z;
    int t  = threadIdx.x;
    float* qp = g_qkv + (size_t)b * OC * NPOS + (size_t)(h * CH) * NPOS + n0 + t;
#pragma unroll 4
    for (int d = 0; d < CH; d++) sq[d][t] = qp[(size_t)d * NPOS];
    float mx = -1e30f;
#pragma unroll 4
    for (int d = 0; d < CH; d++) mx = fmaxf(mx, sq[d][t]);
    float s = 0.f;
#pragma unroll 4
    for (int d = 0; d < CH; d++) {
        float e = __expf(sq[d][t] - mx);
        sq[d][t] = e; s += e;
    }
    float r = QSCALE / s;
#pragma unroll 4
    for (int d = 0; d < CH; d++) qp[(size_t)d * NPOS] = sq[d][t] * r;
}

// -------------------------------------------------- k softmax over n=4096 (row)
__device__ __forceinline__ float block_reduce(float v, bool is_max)
{
    __shared__ float sred[32];
#pragma unroll
    for (int o = 16; o; o >>= 1) {
        float u = __shfl_xor_sync(0xffffffff, v, o);
        v = is_max ? fmaxf(v, u) : v + u;
    }
    int w = threadIdx.x >> 5;
    __syncthreads();                       // protect previous sred use
    if ((threadIdx.x & 31) == 0) sred[w] = v;
    __syncthreads();
    if (w == 0) {
        int nw = blockDim.x >> 5;
        v = (threadIdx.x < nw) ? sred[threadIdx.x] : (is_max ? -1e30f : 0.f);
#pragma unroll
        for (int o = 16; o; o >>= 1) {
            float u = __shfl_xor_sync(0xffffffff, v, o);
            v = is_max ? fmaxf(v, u) : v + u;
        }
        if (threadIdx.x == 0) sred[0] = v;
    }
    __syncthreads();
    return sred[0];
}

__global__ void softmax_k_kernel()
{
    __shared__ float row[NPOS];          // 16 KB
    int c = blockIdx.x;                  // 0..383
    int b = blockIdx.y;
    float* kp = g_qkv + (size_t)b * OC * NPOS + (size_t)(CDIM + c) * NPOS;
    int t = threadIdx.x;                 // 256
    float mx = -1e30f;
    for (int i = t; i < NPOS; i += 256) {
        float v = kp[i]; row[i] = v; mx = fmaxf(mx, v);
    }
    mx = block_reduce(mx, true);
    float s = 0.f;
    for (int i = t; i < NPOS; i += 256) {
        float e = __expf(row[i] - mx);
        row[i] = e; s += e;
    }
    s = block_reduce(s, false);
    float r = 1.f / s;
    for (int i = t; i < NPOS; i += 256) kp[i] = row[i] * r;
}

// ---------------------------------------------------------------- zero scratch
__global__ void zero_kernel(float* p, int n)
{
    int i = blockIdx.x * blockDim.x + threadIdx.x;
    if (i < n) p[i] = 0.f;
}

// ---------------------------------- context: ctx[b,h,d,e] = sum_n k[d,n]*v[e,n]
__global__ __launch_bounds__(256)
void context_kernel()
{
    __shared__ float sk[CH][33];
    __shared__ float sv[CH][33];
    int bh = blockIdx.y;                 // 0..63
    int b = bh >> 2, h = bh & 3;
    int n0 = blockIdx.x * 256;
    const float* kp = g_qkv + (size_t)b * OC * NPOS + (size_t)(CDIM     + h * CH) * NPOS;
    const float* vp = g_qkv + (size_t)b * OC * NPOS + (size_t)(2 * CDIM + h * CH) * NPOS;
    int t  = threadIdx.x;
    int ty = t >> 4, tx = t & 15;
    float acc[6][6];
#pragma unroll
    for (int i = 0; i < 6; i++)
#pragma unroll
        for (int j = 0; j < 6; j++) acc[i][j] = 0.f;

    for (int sub = 0; sub < 8; sub++) {
        int nb = n0 + sub * 32;
        __syncthreads();
        for (int idx = t; idx < CH * 32; idx += 256) {
            int d = idx >> 5, j = idx & 31;
            sk[d][j] = kp[(size_t)d * NPOS + nb + j];
            sv[d][j] = vp[(size_t)d * NPOS + nb + j];
        }
        __syncthreads();
#pragma unroll 8
        for (int jj = 0; jj < 32; jj++) {
            float ka[6], vb[6];
#pragma unroll
            for (int i = 0; i < 6; i++) ka[i] = sk[ty + 16 * i][jj];
#pragma unroll
            for (int j = 0; j < 6; j++) vb[j] = sv[tx + 16 * j][jj];
#pragma unroll
            for (int i = 0; i < 6; i++)
#pragma unroll
                for (int j = 0; j < 6; j++)
                    acc[i][j] = fmaf(ka[i], vb[j], acc[i][j]);
        }
    }
    float* cx = g_ctx + (size_t)bh * CH * CH;
#pragma unroll
    for (int i = 0; i < 6; i++)
#pragma unroll
        for (int j = 0; j < 6; j++)
            atomicAdd(&cx[(ty + 16 * i) * CH + (tx + 16 * j)], acc[i][j]);
}

// ------------- fold ctx into Wout:  W2[b][o][h*96+d] = sum_e Wout[o][h*96+e]*ctx
__global__ void w2_kernel(const float* __restrict__ Wout)
{
    __shared__ float sc[CH][CH + 1];
    int h = blockIdx.x & 3;
    int b = blockIdx.x >> 2;
    const float* cx = g_ctx + (size_t)(b * HEADS + h) * CH * CH;
    int t = threadIdx.x;
    for (int idx = t; idx < CH * CH; idx += 256)
        sc[idx / CH][idx % CH] = cx[idx];
    __syncthreads();
    for (int idx = t; idx < CDIM * CH; idx += 256) {
        int o = idx / CH, d = idx % CH;
        const float* wr = Wout + (size_t)o * CDIM + h * CH;
        float a = 0.f;
#pragma unroll 8
        for (int e = 0; e < CH; e++) a = fmaf(wr[e], sc[d][e], a);
        g_w2[(size_t)b * CDIM * CDIM + (size_t)o * CDIM + h * CH + d] = a;
    }
}

// ------------------------------------------- output LN + residual -> d_out
__global__ void ln_out_kernel(const float* __restrict__ g,
                              float* __restrict__ out)
{
    int n = blockIdx.x * blockDim.x + threadIdx.x;
    int b = blockIdx.y;
    const float* yp  = g_out2 + (size_t)b * CDIM * NPOS + n;
    const float* xnp = g_xn   + (size_t)b * CDIM * NPOS + n;
    float s = 0.f, ss = 0.f;
#pragma unroll 8
    for (int c = 0; c < CDIM; c++) {
        float v = yp[(size_t)c * NPOS];
        s += v; ss += v * v;
    }
    float mean = s * (1.f / CDIM);
    float var  = ss * (1.f / CDIM) - mean * mean;
    float inv  = rsqrtf(var + 1e-5f);
    float* op = out + (size_t)b * CDIM * NPOS + n;
#pragma unroll 8
    for (int c = 0; c < CDIM; c++)
        op[(size_t)c * NPOS] =
            (yp[(size_t)c * NPOS] - mean) * inv * g[c] + xnp[(size_t)c * NPOS];
}

// ---------------------------------------------------------------------------
extern "C" void kernel_launch(void* const* d_in, const int* in_sizes, int n_in,
                              void* d_out, int out_size)
{
    const float* x         = (const float*)d_in[0];
    const float* prenorm_g = (const float*)d_in[1];
    const float* Wqkv      = (const float*)d_in[2];
    const float* Wout      = (const float*)d_in[3];
    const float* bout      = (const float*)d_in[4];
    const float* outnorm_g = (const float*)d_in[5];
    float* out = (float*)d_out;

    float *p_xn, *p_qkv, *p_ctx, *p_w2, *p_out2;
    cudaGetSymbolAddress((void**)&p_xn,   g_xn);
    cudaGetSymbolAddress((void**)&p_qkv,  g_qkv);
    cudaGetSymbolAddress((void**)&p_ctx,  g_ctx);
    cudaGetSymbolAddress((void**)&p_w2,   g_w2);
    cudaGetSymbolAddress((void**)&p_out2, g_out2);

    // 1. prenorm
    ln_pre_kernel<<<dim3(NPOS / 128, BATCH), 128>>>(x, prenorm_g);

    // 2. qkv = Wqkv @ xn   (M=1152, N=4096, K=384, batched over 16)
    sgemm_kernel<false><<<dim3(NPOS / 128, OC / 128, BATCH), 256>>>(
        Wqkv, 0LL,
        p_xn,  (long long)CDIM * NPOS,
        p_qkv, (long long)OC * NPOS,
        nullptr, OC, NPOS, CDIM);

    // 3. softmaxes (in place)
    softmax_q_kernel<<<dim3(NPOS / 128, HEADS, BATCH), 128>>>();
    softmax_k_kernel<<<dim3(CDIM, BATCH), 256>>>();

    // 4. context
    int ctx_elems = BATCH * HEADS * CH * CH;
    zero_kernel<<<(ctx_elems + 255) / 256, 256>>>(p_ctx, ctx_elems);
    context_kernel<<<dim3(NPOS / 256, BATCH * HEADS), 256>>>();

    // 5. fold ctx into Wout
    w2_kernel<<<BATCH * HEADS, 256>>>(Wout);

    // 6. out2 = W2 @ q + bout  (M=384, N=4096, K=384, batched)
    sgemm_kernel<true><<<dim3(NPOS / 128, CDIM / 128, BATCH), 256>>>(
        p_w2,  (long long)CDIM * CDIM,
        p_qkv, (long long)OC * NPOS,        // q region = offset 0
        p_out2,(long long)CDIM * NPOS,
        bout, CDIM, NPOS, CDIM);

    // 7. output LN + residual
    ln_out_kernel<<<dim3(NPOS / 128, BATCH), 128>>>(outnorm_g, out);
}

// round 5
// speedup vs baseline: 3.0858x; 3.0858x over previous
#include <cuda_runtime.h>
#include <cstdint>

// ---------------------------------------------------------------------------
// LinearAttention:  b=16, dim=384, n=64*64=4096, heads=4, ch=96
//  1. xn = chanLN(x) * prenorm_g
//  2. qkv = Wqkv @ xn                       (TF32 tensor-core GEMM)
//  3. q = softmax over ch * scale ; k = softmax over n
//  4. ctx[d,e] = sum_n k[d,n] v[e,n]        (TF32 tensor-core, split-K)
//  5. W2[o, h*96+d] = sum_e Wout[o, h*96+e] * ctx[b,h,d,e]
//  6. out2 = W2 @ q + bout                  (TF32 tensor-core GEMM)
//  7. out = chanLN(out2)*outnorm_g + xn
// ---------------------------------------------------------------------------

#define BATCH 16
#define CDIM  384
#define NPOS  4096
#define HEADS 4
#define CH    96
#define OC    1152
#define QSCALE 0.1020620726159658f

static __device__ float g_xn  [BATCH * CDIM * NPOS];
static __device__ float g_qkv [BATCH * OC   * NPOS];
static __device__ float g_ctx [BATCH * HEADS * CH * CH];
static __device__ float g_w2  [BATCH * CDIM * CDIM];
static __device__ float g_out2[BATCH * CDIM * NPOS];

// ------------------------------------------------------------- mma helpers
__device__ __forceinline__ uint32_t cvt_tf32(float x) {
    uint32_t r;
    asm("cvt.rna.tf32.f32 %0, %1;" : "=r"(r) : "f"(x));
    return r;
}
__device__ __forceinline__ void mma8(float* d, const uint32_t* a, const uint32_t* b) {
    asm volatile(
        "mma.sync.aligned.m16n8k8.row.col.f32.tf32.tf32.f32 "
        "{%0,%1,%2,%3}, {%4,%5,%6,%7}, {%8,%9}, {%0,%1,%2,%3};"
        : "+f"(d[0]), "+f"(d[1]), "+f"(d[2]), "+f"(d[3])
        : "r"(a[0]), "r"(a[1]), "r"(a[2]), "r"(a[3]), "r"(b[0]), "r"(b[1]));
}
__device__ __forceinline__ void cp_async16(uint32_t saddr, const void* g) {
    asm volatile("cp.async.ca.shared.global [%0], [%1], 16;" :: "r"(saddr), "l"(g));
}
__device__ __forceinline__ void cp_commit() { asm volatile("cp.async.commit_group;"); }
template<int N>
__device__ __forceinline__ void cp_wait() { asm volatile("cp.async.wait_group %0;" :: "n"(N)); }

// ---------------------------------------------------------------- prenorm LN
__global__ void ln_pre_kernel(const float* __restrict__ x,
                              const float* __restrict__ g)
{
    int n = blockIdx.x * blockDim.x + threadIdx.x;
    int b = blockIdx.y;
    const float* xp = x + (size_t)b * CDIM * NPOS + n;
    float s = 0.f, ss = 0.f;
#pragma unroll 8
    for (int c = 0; c < CDIM; c++) {
        float v = xp[(size_t)c * NPOS];
        s += v; ss += v * v;
    }
    float mean = s * (1.f / CDIM);
    float var  = ss * (1.f / CDIM) - mean * mean;
    float inv  = rsqrtf(var + 1e-5f);
    float* op = g_xn + (size_t)b * CDIM * NPOS + n;
#pragma unroll 8
    for (int c = 0; c < CDIM; c++)
        op[(size_t)c * NPOS] = (xp[(size_t)c * NPOS] - mean) * inv * g[c];
}

// ---------------------------------------------- TF32 GEMM 128x128x32, 8 warps
// C[bz] (MxN) = A[bz] (MxK row-major) * B[bz] (KxN row-major)  (+ bias[m])
// smem: As [2][128][36] ([m][k], stride 36 -> conflict-free frags)
//       Bs [2][32][136] ([k][n], stride 136 -> conflict-free frags)
#define GM_AS (128 * 36)
#define GM_BS (32 * 136)
#define GEMM_SMEM ((2 * GM_AS + 2 * GM_BS) * 4)

#define GEMM_LOAD_STAGE(s, k0)                                                  \
    {                                                                           \
        _Pragma("unroll")                                                       \
        for (int c = 0; c < 4; c++) {                                           \
            int chunk = tid + c * 256;                                          \
            int mm = chunk >> 3, kc = (chunk & 7) * 4;                          \
            cp_async16(as_base + (uint32_t)(((s) * GM_AS + mm * 36 + kc) * 4),  \
                       Ab + (size_t)(m0 + mm) * K + (k0) + kc);                 \
        }                                                                       \
        _Pragma("unroll")                                                       \
        for (int c = 0; c < 4; c++) {                                           \
            int chunk = tid + c * 256;                                          \
            int kr = chunk >> 5, nc = (chunk & 31) * 4;                         \
            cp_async16(bs_base + (uint32_t)(((s) * GM_BS + kr * 136 + nc) * 4), \
                       Bb + (size_t)((k0) + kr) * N + n0 + nc);                 \
        }                                                                       \
        cp_commit();                                                            \
    }

template<bool BIAS>
__global__ __launch_bounds__(256, 2)
void mma_gemm_kernel(const float* __restrict__ A, long long sA,
                     const float* __restrict__ B, long long sB,
                     float* __restrict__ C, long long sC,
                     const float* __restrict__ bias,
                     int M, int N, int K)
{
    extern __shared__ float sm[];
    float* As = sm;
    float* Bs = sm + 2 * GM_AS;
    uint32_t as_base = (uint32_t)__cvta_generic_to_shared(As);
    uint32_t bs_base = (uint32_t)__cvta_generic_to_shared(Bs);

    const float* Ab = A + sA * blockIdx.z;
    const float* Bb = B + sB * blockIdx.z;
    float*       Cb = C + sC * blockIdx.z;
    int m0 = blockIdx.y * 128, n0 = blockIdx.x * 128;
    int tid = threadIdx.x, lane = tid & 31, warp = tid >> 5;
    int wm = (warp >> 2) * 64, wn = (warp & 3) * 32;   // 2x4 warp grid, 64x32 tiles

    float acc[4][4][4];
#pragma unroll
    for (int i = 0; i < 4; i++)
#pragma unroll
        for (int j = 0; j < 4; j++)
#pragma unroll
            for (int r = 0; r < 4; r++) acc[i][j][r] = 0.f;

    int nIter = K / 32;
    GEMM_LOAD_STAGE(0, 0)

    for (int it = 0; it < nIter; it++) {
        if (it + 1 < nIter) {
            GEMM_LOAD_STAGE((it + 1) & 1, (it + 1) * 32)
            cp_wait<1>();
        } else {
            cp_wait<0>();
        }
        __syncthreads();

        const float* Ast = As + (it & 1) * GM_AS;
        const float* Bst = Bs + (it & 1) * GM_BS;
#pragma unroll
        for (int k8 = 0; k8 < 4; k8++) {
            int kk = k8 * 8;
            uint32_t a[4][4], b[4][2];
#pragma unroll
            for (int mf = 0; mf < 4; mf++) {
                int mr = wm + mf * 16 + (lane >> 2);
                a[mf][0] = cvt_tf32(Ast[mr * 36 + kk + (lane & 3)]);
                a[mf][1] = cvt_tf32(Ast[(mr + 8) * 36 + kk + (lane & 3)]);
                a[mf][2] = cvt_tf32(Ast[mr * 36 + kk + (lane & 3) + 4]);
                a[mf][3] = cvt_tf32(Ast[(mr + 8) * 36 + kk + (lane & 3) + 4]);
            }
#pragma unroll
            for (int nf = 0; nf < 4; nf++) {
                int nc = wn + nf * 8 + (lane >> 2);
                b[nf][0] = cvt_tf32(Bst[(kk + (lane & 3)) * 136 + nc]);
                b[nf][1] = cvt_tf32(Bst[(kk + (lane & 3) + 4) * 136 + nc]);
            }
#pragma unroll
            for (int mf = 0; mf < 4; mf++)
#pragma unroll
                for (int nf = 0; nf < 4; nf++)
                    mma8(acc[mf][nf], a[mf], b[nf]);
        }
        __syncthreads();
    }

#pragma unroll
    for (int mf = 0; mf < 4; mf++) {
        int r0 = m0 + wm + mf * 16 + (lane >> 2);
        float bi0 = BIAS ? bias[r0] : 0.f;
        float bi1 = BIAS ? bias[r0 + 8] : 0.f;
#pragma unroll
        for (int nf = 0; nf < 4; nf++) {
            int cc = n0 + wn + nf * 8 + 2 * (lane & 3);
            *(float2*)&Cb[(size_t)r0 * N + cc] =
                make_float2(acc[mf][nf][0] + bi0, acc[mf][nf][1] + bi0);
            *(float2*)&Cb[(size_t)(r0 + 8) * N + cc] =
                make_float2(acc[mf][nf][2] + bi1, acc[mf][nf][3] + bi1);
        }
    }
}

// -------------------------------------------- q softmax over 96 channels, *scale
__global__ void softmax_q_kernel()
{
    __shared__ float sq[CH][128];
    int n0 = blockIdx.x * 128;
    int h  = blockIdx.y;
    int b  = blockIdx.z;
    int t  = threadIdx.x;
    float* qp = g_qkv + (size_t)b * OC * NPOS + (size_t)(h * CH) * NPOS + n0 + t;
#pragma unroll 4
    for (int d = 0; d < CH; d++) sq[d][t] = qp[(size_t)d * NPOS];
    float mx = -1e30f;
#pragma unroll 4
    for (int d = 0; d < CH; d++) mx = fmaxf(mx, sq[d][t]);
    float s = 0.f;
#pragma unroll 4
    for (int d = 0; d < CH; d++) {
        float e = __expf(sq[d][t] - mx);
        sq[d][t] = e; s += e;
    }
    float r = QSCALE / s;
#pragma unroll 4
    for (int d = 0; d < CH; d++) qp[(size_t)d * NPOS] = sq[d][t] * r;
}

// -------------------------------------------------- k softmax over n=4096
__device__ __forceinline__ float block_reduce(float v, bool is_max)
{
    __shared__ float sred[32];
#pragma unroll
    for (int o = 16; o; o >>= 1) {
        float u = __shfl_xor_sync(0xffffffff, v, o);
        v = is_max ? fmaxf(v, u) : v + u;
    }
    int w = threadIdx.x >> 5;
    __syncthreads();
    if ((threadIdx.x & 31) == 0) sred[w] = v;
    __syncthreads();
    if (w == 0) {
        int nw = blockDim.x >> 5;
        v = (threadIdx.x < nw) ? sred[threadIdx.x] : (is_max ? -1e30f : 0.f);
#pragma unroll
        for (int o = 16; o; o >>= 1) {
            float u = __shfl_xor_sync(0xffffffff, v, o);
            v = is_max ? fmaxf(v, u) : v + u;
        }
        if (threadIdx.x == 0) sred[0] = v;
    }
    __syncthreads();
    return sred[0];
}

__global__ void softmax_k_kernel()
{
    __shared__ float row[NPOS];
    int c = blockIdx.x;
    int b = blockIdx.y;
    float* kp = g_qkv + (size_t)b * OC * NPOS + (size_t)(CDIM + c) * NPOS;
    int t = threadIdx.x;
    float mx = -1e30f;
    for (int i = t; i < NPOS; i += 256) {
        float v = kp[i]; row[i] = v; mx = fmaxf(mx, v);
    }
    mx = block_reduce(mx, true);
    float s = 0.f;
    for (int i = t; i < NPOS; i += 256) {
        float e = __expf(row[i] - mx);
        row[i] = e; s += e;
    }
    s = block_reduce(s, false);
    float r = 1.f / s;
    for (int i = t; i < NPOS; i += 256) kp[i] = row[i] * r;
}

// ---------------------------------------------------------------- zero scratch
__global__ void zero_kernel(float* p, int n)
{
    int i = blockIdx.x * blockDim.x + threadIdx.x;
    if (i < n) p[i] = 0.f;
}

// --------------------- context (TF32 mma): ctx[d,e] = sum_n k[d,n] v[e,n]
// A = k tile [96][nk], B = v tile [96][nk]; both [row][n] stride 36.
// split-K over n: each block does 1024 positions, atomicAdd into g_ctx.
#define CTX_TS  (96 * 36)          // per-stage floats (one operand)
#define CTX_SMEM (4 * CTX_TS * 4)  // 2 stages x 2 operands

#define CTX_LOAD_STAGE(s, kk0)                                                  \
    {                                                                           \
        _Pragma("unroll")                                                       \
        for (int c = 0; c < 3; c++) {                                           \
            int chunk = tid + c * 256;                                          \
            int rr = chunk >> 3, kc = (chunk & 7) * 4;                          \
            cp_async16(ks_base + (uint32_t)(((s) * CTX_TS + rr * 36 + kc) * 4), \
                       kp + (size_t)rr * NPOS + (kk0) + kc);                    \
            cp_async16(vs_base + (uint32_t)(((s) * CTX_TS + rr * 36 + kc) * 4), \
                       vp + (size_t)rr * NPOS + (kk0) + kc);                    \
        }                                                                       \
        cp_commit();                                                            \
    }

__global__ __launch_bounds__(256, 2)
void context_kernel()
{
    extern __shared__ float sm[];
    float* Ks = sm;                 // [2][96][36]
    float* Vs = sm + 2 * CTX_TS;    // [2][96][36]
    uint32_t ks_base = (uint32_t)__cvta_generic_to_shared(Ks);
    uint32_t vs_base = (uint32_t)__cvta_generic_to_shared(Vs);

    int bh = blockIdx.y;
    int b = bh >> 2, h = bh & 3;
    int nbase = blockIdx.x * 1024;
    const float* kp = g_qkv + (size_t)b * OC * NPOS + (size_t)(CDIM     + h * CH) * NPOS + nbase;
    const float* vp = g_qkv + (size_t)b * OC * NPOS + (size_t)(2 * CDIM + h * CH) * NPOS + nbase;

    int tid = threadIdx.x, lane = tid & 31, warp = tid >> 5;
    int wm = (warp >> 2) * 48, wn = (warp & 3) * 24;  // 2x4 warps, 48x24 tiles

    float acc[3][3][4];
#pragma unroll
    for (int i = 0; i < 3; i++)
#pragma unroll
        for (int j = 0; j < 3; j++)
#pragma unroll
            for (int r = 0; r < 4; r++) acc[i][j][r] = 0.f;

    CTX_LOAD_STAGE(0, 0)
    for (int it = 0; it < 32; it++) {
        if (it + 1 < 32) {
            CTX_LOAD_STAGE((it + 1) & 1, (it + 1) * 32)
            cp_wait<1>();
        } else {
            cp_wait<0>();
        }
        __syncthreads();

        const float* Kst = Ks + (it & 1) * CTX_TS;
        const float* Vst = Vs + (it & 1) * CTX_TS;
#pragma unroll
        for (int k8 = 0; k8 < 4; k8++) {
            int kk = k8 * 8;
            uint32_t a[3][4], bfr[3][2];
#pragma unroll
            for (int mf = 0; mf < 3; mf++) {
                int mr = wm + mf * 16 + (lane >> 2);
                a[mf][0] = cvt_tf32(Kst[mr * 36 + kk + (lane & 3)]);
                a[mf][1] = cvt_tf32(Kst[(mr + 8) * 36 + kk + (lane & 3)]);
                a[mf][2] = cvt_tf32(Kst[mr * 36 + kk + (lane & 3) + 4]);
                a[mf][3] = cvt_tf32(Kst[(mr + 8) * 36 + kk + (lane & 3) + 4]);
            }
#pragma unroll
            for (int nf = 0; nf < 3; nf++) {
                int er = wn + nf * 8 + (lane >> 2);
                bfr[nf][0] = cvt_tf32(Vst[er * 36 + kk + (lane & 3)]);
                bfr[nf][1] = cvt_tf32(Vst[er * 36 + kk + (lane & 3) + 4]);
            }
#pragma unroll
            for (int mf = 0; mf < 3; mf++)
#pragma unroll
                for (int nf = 0; nf < 3; nf++)
                    mma8(acc[mf][nf], a[mf], bfr[nf]);
        }
        __syncthreads();
    }

    float* cx = g_ctx + (size_t)bh * CH * CH;
#pragma unroll
    for (int mf = 0; mf < 3; mf++) {
        int r0 = wm + mf * 16 + (lane >> 2);
#pragma unroll
        for (int nf = 0; nf < 3; nf++) {
            int cc = wn + nf * 8 + 2 * (lane & 3);
            atomicAdd(&cx[r0 * CH + cc],           acc[mf][nf][0]);
            atomicAdd(&cx[r0 * CH + cc + 1],       acc[mf][nf][1]);
            atomicAdd(&cx[(r0 + 8) * CH + cc],     acc[mf][nf][2]);
            atomicAdd(&cx[(r0 + 8) * CH + cc + 1], acc[mf][nf][3]);
        }
    }
}

// ------------- fold ctx into Wout:  W2[b][o][h*96+d] = sum_e Wout[o][h*96+e]*ctx
__global__ void w2_kernel(const float* __restrict__ Wout)
{
    __shared__ float sc[CH][CH + 1];
    int h = blockIdx.x & 3;
    int b = blockIdx.x >> 2;
    const float* cx = g_ctx + (size_t)(b * HEADS + h) * CH * CH;
    int t = threadIdx.x;
    for (int idx = t; idx < CH * CH; idx += 256)
        sc[idx / CH][idx % CH] = cx[idx];
    __syncthreads();
    for (int idx = t; idx < CDIM * CH; idx += 256) {
        int o = idx / CH, d = idx % CH;
        const float* wr = Wout + (size_t)o * CDIM + h * CH;
        float a = 0.f;
#pragma unroll 8
        for (int e = 0; e < CH; e++) a = fmaf(wr[e], sc[d][e], a);
        g_w2[(size_t)b * CDIM * CDIM + (size_t)o * CDIM + h * CH + d] = a;
    }
}

// ------------------------------------------- output LN + residual -> d_out
__global__ void ln_out_kernel(const float* __restrict__ g,
                              float* __restrict__ out)
{
    int n = blockIdx.x * blockDim.x + threadIdx.x;
    int b = blockIdx.y;
    const float* yp  = g_out2 + (size_t)b * CDIM * NPOS + n;
    const float* xnp = g_xn   + (size_t)b * CDIM * NPOS + n;
    float s = 0.f, ss = 0.f;
#pragma unroll 8
    for (int c = 0; c < CDIM; c++) {
        float v = yp[(size_t)c * NPOS];
        s += v; ss += v * v;
    }
    float mean = s * (1.f / CDIM);
    float var  = ss * (1.f / CDIM) - mean * mean;
    float inv  = rsqrtf(var + 1e-5f);
    float* op = out + (size_t)b * CDIM * NPOS + n;
#pragma unroll 8
    for (int c = 0; c < CDIM; c++)
        op[(size_t)c * NPOS] =
            (yp[(size_t)c * NPOS] - mean) * inv * g[c] + xnp[(size_t)c * NPOS];
}

// ---------------------------------------------------------------------------
extern "C" void kernel_launch(void* const* d_in, const int* in_sizes, int n_in,
                              void* d_out, int out_size)
{
    const float* x         = (const float*)d_in[0];
    const float* prenorm_g = (const float*)d_in[1];
    const float* Wqkv      = (const float*)d_in[2];
    const float* Wout      = (const float*)d_in[3];
    const float* bout      = (const float*)d_in[4];
    const float* outnorm_g = (const float*)d_in[5];
    float* out = (float*)d_out;

    float *p_xn, *p_qkv, *p_ctx, *p_w2, *p_out2;
    cudaGetSymbolAddress((void**)&p_xn,   g_xn);
    cudaGetSymbolAddress((void**)&p_qkv,  g_qkv);
    cudaGetSymbolAddress((void**)&p_ctx,  g_ctx);
    cudaGetSymbolAddress((void**)&p_w2,   g_w2);
    cudaGetSymbolAddress((void**)&p_out2, g_out2);

    cudaFuncSetAttribute(mma_gemm_kernel<false>,
                         cudaFuncAttributeMaxDynamicSharedMemorySize, GEMM_SMEM);
    cudaFuncSetAttribute(mma_gemm_kernel<true>,
                         cudaFuncAttributeMaxDynamicSharedMemorySize, GEMM_SMEM);
    cudaFuncSetAttribute(context_kernel,
                         cudaFuncAttributeMaxDynamicSharedMemorySize, CTX_SMEM);

    // 1. prenorm
    ln_pre_kernel<<<dim3(NPOS / 128, BATCH), 128>>>(x, prenorm_g);

    // 2. qkv = Wqkv @ xn   (M=1152, N=4096, K=384, batched over 16)
    mma_gemm_kernel<false><<<dim3(NPOS / 128, OC / 128, BATCH), 256, GEMM_SMEM>>>(
        Wqkv, 0LL,
        p_xn,  (long long)CDIM * NPOS,
        p_qkv, (long long)OC * NPOS,
        nullptr, OC, NPOS, CDIM);

    // 3. softmaxes (in place)
    softmax_q_kernel<<<dim3(NPOS / 128, HEADS, BATCH), 128>>>();
    softmax_k_kernel<<<dim3(CDIM, BATCH), 256>>>();

    // 4. context (tensor core, split-K=4 over n)
    int ctx_elems = BATCH * HEADS * CH * CH;
    zero_kernel<<<(ctx_elems + 255) / 256, 256>>>(p_ctx, ctx_elems);
    context_kernel<<<dim3(4, BATCH * HEADS), 256, CTX_SMEM>>>();

    // 5. fold ctx into Wout
    w2_kernel<<<BATCH * HEADS, 256>>>(Wout);

    // 6. out2 = W2 @ q + bout  (M=384, N=4096, K=384, batched)
    mma_gemm_kernel<true><<<dim3(NPOS / 128, CDIM / 128, BATCH), 256, GEMM_SMEM>>>(
        p_w2,  (long long)CDIM * CDIM,
        p_qkv, (long long)OC * NPOS,        // q region = offset 0
        p_out2,(long long)CDIM * NPOS,
        bout, CDIM, NPOS, CDIM);

    // 7. output LN + residual
    ln_out_kernel<<<dim3(NPOS / 128, BATCH), 128>>>(outnorm_g, out);
}

// round 10
// speedup vs baseline: 3.5482x; 1.1499x over previous
#include <cuda_runtime.h>
#include <cuda_bf16.h>
#include <cstdint>

// ---------------------------------------------------------------------------
// LinearAttention (b=16, dim=384, n=4096, heads=4, ch=96) — bf16 tensor cores.
//  1. ln_pre: stats(x) -> (mean,inv); writes xnT bf16 [n][c]
//  2. qkv = Wqkv @ xn           (bf16 MMA GEMM, bf16 out)
//  3. softmax_q -> qT bf16 [n][c] ; softmax_k -> k bf16 [c][n]
//  4. ctx = k @ v^T per (b,h)   (bf16 MMA, split-K + atomics)
//  5. W2 = fold(Wout, ctx) bf16
//  6. out2 = W2 @ q + bout      (bf16 MMA, f32 out)
//  7. ln_out: chanLN(out2)*g + recompute(xn from x, stats)
// ---------------------------------------------------------------------------

typedef __nv_bfloat16 bf16;

#define BATCH 16
#define CDIM  384
#define NPOS  4096
#define HEADS 4
#define CH    96
#define OC    1152
#define QSCALE 0.1020620726159658f

static __device__ bf16   g_wqkvb[OC * CDIM];
static __device__ bf16   g_xnT [BATCH * NPOS * CDIM];        // [b][n][c]
static __device__ float2 g_stats[BATCH * NPOS];              // (mean, inv)
static __device__ bf16   g_qkvb[BATCH * OC * NPOS];          // [b][1152][n]
static __device__ bf16   g_kb  [BATCH * CDIM * NPOS];        // softmaxed k
static __device__ bf16   g_qT  [BATCH * NPOS * CDIM];        // softmaxed q, [n][c]
static __device__ float  g_ctx [BATCH * HEADS * CH * CH];
static __device__ bf16   g_w2b [BATCH * CDIM * CDIM];
static __device__ float  g_out2[BATCH * CDIM * NPOS];

// ------------------------------------------------------------- helpers
__device__ __forceinline__ void mma16(float* d, const uint32_t* a, const uint32_t* b) {
    asm volatile(
        "mma.sync.aligned.m16n8k16.row.col.f32.bf16.bf16.f32 "
        "{%0,%1,%2,%3}, {%4,%5,%6,%7}, {%8,%9}, {%0,%1,%2,%3};"
        : "+f"(d[0]), "+f"(d[1]), "+f"(d[2]), "+f"(d[3])
        : "r"(a[0]), "r"(a[1]), "r"(a[2]), "r"(a[3]), "r"(b[0]), "r"(b[1]));
}
__device__ __forceinline__ void cp_async16(uint32_t saddr, const void* g) {
    asm volatile("cp.async.ca.shared.global [%0], [%1], 16;" :: "r"(saddr), "l"(g));
}
__device__ __forceinline__ void cp_commit() { asm volatile("cp.async.commit_group;"); }
template<int N>
__device__ __forceinline__ void cp_wait() { asm volatile("cp.async.wait_group %0;" :: "n"(N)); }

// --------------------------------------------------- Wqkv f32 -> bf16
__global__ void conv_wqkv_kernel(const float* __restrict__ w)
{
    int i = blockIdx.x * blockDim.x + threadIdx.x;
    if (i < OC * CDIM) g_wqkvb[i] = __float2bfloat16_rn(w[i]);
}

// -------------------------------------- prenorm: stats + transposed bf16 xn
__global__ void ln_pre_kernel(const float* __restrict__ x,
                              const float* __restrict__ g)
{
    __shared__ float tile[32][129];
    int t = threadIdx.x;                 // 128
    int n0 = blockIdx.x * 128;
    int n = n0 + t;
    int b = blockIdx.y;
    const float* xp = x + (size_t)b * CDIM * NPOS + n;

    float s = 0.f, ss = 0.f;
#pragma unroll 8
    for (int c = 0; c < CDIM; c++) {
        float v = xp[(size_t)c * NPOS];
        s += v; ss += v * v;
    }
    float mean = s * (1.f / CDIM);
    float var  = ss * (1.f / CDIM) - mean * mean;
    float inv  = rsqrtf(var + 1e-5f);
    g_stats[b * NPOS + n] = make_float2(mean, inv);

    bf16* xnT = g_xnT + (size_t)b * NPOS * CDIM;
    for (int c0 = 0; c0 < CDIM; c0 += 32) {
#pragma unroll
        for (int i = 0; i < 32; i++)
            tile[i][t] = (xp[(size_t)(c0 + i) * NPOS] - mean) * inv * g[c0 + i];
        __syncthreads();
        for (int idx = t; idx < 128 * 16; idx += 128) {
            int rr = idx >> 4, pp = idx & 15;
            __nv_bfloat162 p = __floats2bfloat162_rn(tile[2 * pp][rr], tile[2 * pp + 1][rr]);
            *(__nv_bfloat162*)&xnT[(size_t)(n0 + rr) * CDIM + c0 + 2 * pp] = p;
        }
        __syncthreads();
    }
}

// ---------------------------- bf16 GEMM 128x128x32, 8 warps (64x32 tiles)
// C = A[M][K] * B[N][K]^T ; A,B bf16 k-contiguous; C f32 (+bias) or bf16.
#define GAS    40                 // smem k-stride (bf16)
#define GM_ASZ (128 * GAS)        // per-stage elems per operand
#define GEMM_SMEM (4 * GM_ASZ * 2)

#define GLOAD(s, k0)                                                            \
    {                                                                           \
        _Pragma("unroll")                                                       \
        for (int c = 0; c < 2; c++) {                                           \
            int chunk = tid + c * 256;                                          \
            int mm = chunk >> 2, kc = (chunk & 3) * 8;                          \
            cp_async16(as_base + (uint32_t)(((s) * GM_ASZ + mm * GAS + kc) * 2),\
                       Ab + (size_t)(m0 + mm) * K + (k0) + kc);                 \
            cp_async16(bs_base + (uint32_t)(((s) * GM_ASZ + mm * GAS + kc) * 2),\
                       Bb + (size_t)(n0 + mm) * K + (k0) + kc);                 \
        }                                                                       \
        cp_commit();                                                            \
    }

template<bool BIAS, bool OUTBF>
__global__ __launch_bounds__(256, 2)
void mma_gemm_kernel(const bf16* __restrict__ A, long long sA,
                     const bf16* __restrict__ B, long long sB,
                     void* __restrict__ Cv, long long sC,
                     const float* __restrict__ bias,
                     int M, int N, int K)
{
    extern __shared__ bf16 smb[];
    bf16* As = smb;
    bf16* Bs = smb + 2 * GM_ASZ;
    uint32_t as_base = (uint32_t)__cvta_generic_to_shared(As);
    uint32_t bs_base = (uint32_t)__cvta_generic_to_shared(Bs);

    int bz = blockIdx.z;
    const bf16* Ab = A + sA * bz;
    const bf16* Bb = B + sB * bz;
    int m0 = blockIdx.y * 128, n0 = blockIdx.x * 128;
    int tid = threadIdx.x, lane = tid & 31, warp = tid >> 5;
    int wm = (warp >> 2) * 64, wn = (warp & 3) * 32;

    float acc[4][4][4];
#pragma unroll
    for (int i = 0; i < 4; i++)
#pragma unroll
        for (int j = 0; j < 4; j++)
#pragma unroll
            for (int r = 0; r < 4; r++) acc[i][j][r] = 0.f;

    int nIter = K / 32;
    GLOAD(0, 0)

    for (int it = 0; it < nIter; it++) {
        if (it + 1 < nIter) {
            GLOAD((it + 1) & 1, (it + 1) * 32)
            cp_wait<1>();
        } else {
            cp_wait<0>();
        }
        __syncthreads();

        const bf16* Ast = As + (it & 1) * GM_ASZ;
        const bf16* Bst = Bs + (it & 1) * GM_ASZ;
#pragma unroll
        for (int h16 = 0; h16 < 2; h16++) {
            int kk = h16 * 16 + (lane & 3) * 2;
            uint32_t a[4][4], bq[4][2];
#pragma unroll
            for (int mf = 0; mf < 4; mf++) {
                int r = wm + mf * 16 + (lane >> 2);
                a[mf][0] = *(const uint32_t*)&Ast[r * GAS + kk];
                a[mf][1] = *(const uint32_t*)&Ast[(r + 8) * GAS + kk];
                a[mf][2] = *(const uint32_t*)&Ast[r * GAS + kk + 8];
                a[mf][3] = *(const uint32_t*)&Ast[(r + 8) * GAS + kk + 8];
            }
#pragma unroll
            for (int nf = 0; nf < 4; nf++) {
                int nn = wn + nf * 8 + (lane >> 2);
                bq[nf][0] = *(const uint32_t*)&Bst[nn * GAS + kk];
                bq[nf][1] = *(const uint32_t*)&Bst[nn * GAS + kk + 8];
            }
#pragma unroll
            for (int mf = 0; mf < 4; mf++)
#pragma unroll
                for (int nf = 0; nf < 4; nf++)
                    mma16(acc[mf][nf], a[mf], bq[nf]);
        }
        __syncthreads();
    }

    if (OUTBF) {
        bf16* Cb = (bf16*)Cv + (size_t)sC * bz;
#pragma unroll
        for (int mf = 0; mf < 4; mf++) {
            int r0 = m0 + wm + mf * 16 + (lane >> 2);
#pragma unroll
            for (int nf = 0; nf < 4; nf++) {
                int cc = n0 + wn + nf * 8 + 2 * (lane & 3);
                *(__nv_bfloat162*)&Cb[(size_t)r0 * N + cc] =
                    __floats2bfloat162_rn(acc[mf][nf][0], acc[mf][nf][1]);
                *(__nv_bfloat162*)&Cb[(size_t)(r0 + 8) * N + cc] =
                    __floats2bfloat162_rn(acc[mf][nf][2], acc[mf][nf][3]);
            }
        }
    } else {
        float* Cb = (float*)Cv + (size_t)sC * bz;
#pragma unroll
        for (int mf = 0; mf < 4; mf++) {
            int r0 = m0 + wm + mf * 16 + (lane >> 2);
            float bi0 = BIAS ? bias[r0] : 0.f;
            float bi1 = BIAS ? bias[r0 + 8] : 0.f;
#pragma unroll
            for (int nf = 0; nf < 4; nf++) {
                int cc = n0 + wn + nf * 8 + 2 * (lane & 3);
                *(float2*)&Cb[(size_t)r0 * N + cc] =
                    make_float2(acc[mf][nf][0] + bi0, acc[mf][nf][1] + bi0);
                *(float2*)&Cb[(size_t)(r0 + 8) * N + cc] =
                    make_float2(acc[mf][nf][2] + bi1, acc[mf][nf][3] + bi1);
            }
        }
    }
}

// ------------------- q softmax over 96 ch, *scale; emits qT bf16 [n][c]
#define SQ_STRIDE 129
#define SQ_SMEM (CH * SQ_STRIDE * 4)
__global__ void softmax_q_kernel()
{
    extern __shared__ float sq[];     // [96][129]
    int n0 = blockIdx.x * 128;
    int h  = blockIdx.y;
    int b  = blockIdx.z;
    int t  = threadIdx.x;
    const bf16* qp = g_qkvb + (size_t)b * OC * NPOS + (size_t)(h * CH) * NPOS + n0 + t;
#pragma unroll 4
    for (int d = 0; d < CH; d++)
        sq[d * SQ_STRIDE + t] = __bfloat162float(qp[(size_t)d * NPOS]);
    float mx = -1e30f;
#pragma unroll 4
    for (int d = 0; d < CH; d++) mx = fmaxf(mx, sq[d * SQ_STRIDE + t]);
    float s = 0.f;
#pragma unroll 4
    for (int d = 0; d < CH; d++) {
        float e = __expf(sq[d * SQ_STRIDE + t] - mx);
        sq[d * SQ_STRIDE + t] = e; s += e;
    }
    float r = QSCALE / s;
#pragma unroll 4
    for (int d = 0; d < CH; d++) sq[d * SQ_STRIDE + t] *= r;
    __syncthreads();

    bf16* qT = g_qT + (size_t)b * NPOS * CDIM;
    for (int idx = t; idx < 128 * (CH / 2); idx += 128) {
        int rr = idx / (CH / 2), pp = idx - rr * (CH / 2);
        __nv_bfloat162 p = __floats2bfloat162_rn(sq[(2 * pp) * SQ_STRIDE + rr],
                                                 sq[(2 * pp + 1) * SQ_STRIDE + rr]);
        *(__nv_bfloat162*)&qT[(size_t)(n0 + rr) * CDIM + h * CH + 2 * pp] = p;
    }
}

// -------------------------------------- k softmax over n=4096; bf16 in/out
__device__ __forceinline__ float block_reduce(float v, bool is_max)
{
    __shared__ float sred[32];
#pragma unroll
    for (int o = 16; o; o >>= 1) {
        float u = __shfl_xor_sync(0xffffffff, v, o);
        v = is_max ? fmaxf(v, u) : v + u;
    }
    int w = threadIdx.x >> 5;
    __syncthreads();
    if ((threadIdx.x & 31) == 0) sred[w] = v;
    __syncthreads();
    if (w == 0) {
        int nw = blockDim.x >> 5;
        v = (threadIdx.x < nw) ? sred[threadIdx.x] : (is_max ? -1e30f : 0.f);
#pragma unroll
        for (int o = 16; o; o >>= 1) {
            float u = __shfl_xor_sync(0xffffffff, v, o);
            v = is_max ? fmaxf(v, u) : v + u;
        }
        if (threadIdx.x == 0) sred[0] = v;
    }
    __syncthreads();
    return sred[0];
}

__global__ void softmax_k_kernel()
{
    __shared__ float row[NPOS];
    int c = blockIdx.x;
    int b = blockIdx.y;
    const bf16* kin = g_qkvb + (size_t)b * OC * NPOS + (size_t)(CDIM + c) * NPOS;
    bf16* kout = g_kb + (size_t)b * CDIM * NPOS + (size_t)c * NPOS;
    int t = threadIdx.x;
    float mx = -1e30f;
    for (int i = t; i < NPOS; i += 256) {
        float v = __bfloat162float(kin[i]); row[i] = v; mx = fmaxf(mx, v);
    }
    mx = block_reduce(mx, true);
    float s = 0.f;
    for (int i = t; i < NPOS; i += 256) {
        float e = __expf(row[i] - mx);
        row[i] = e; s += e;
    }
    s = block_reduce(s, false);
    float r = 1.f / s;
    for (int i = t; i < NPOS; i += 256) kout[i] = __float2bfloat16_rn(row[i] * r);
}

// ---------------------------------------------------------------- zero scratch
__global__ void zero_kernel(float* p, int n)
{
    int i = blockIdx.x * blockDim.x + threadIdx.x;
    if (i < n) p[i] = 0.f;
}

// ------------- context (bf16 mma): ctx[d,e] = sum_n k[d,n] v[e,n]; split-K=4
#define CTS      72               // smem k-stride (bf16), K-tile 64
#define CTX_ELEM (96 * CTS)
#define CTX_SMEM (4 * CTX_ELEM * 2)

#define CLOAD(s, kk0)                                                           \
    {                                                                           \
        _Pragma("unroll")                                                       \
        for (int c = 0; c < 3; c++) {                                           \
            int chunk = tid + c * 256;                                          \
            int rr = chunk >> 3, kc = (chunk & 7) * 8;                          \
            cp_async16(ks_base + (uint32_t)(((s) * CTX_ELEM + rr * CTS + kc) * 2),\
                       kp + (size_t)rr * NPOS + (kk0) + kc);                    \
            cp_async16(vs_base + (uint32_t)(((s) * CTX_ELEM + rr * CTS + kc) * 2),\
                       vp + (size_t)rr * NPOS + (kk0) + kc);                    \
        }                                                                       \
        cp_commit();                                                            \
    }

__global__ __launch_bounds__(256, 2)
void context_kernel()
{
    extern __shared__ bf16 smc[];
    bf16* Ks = smc;
    bf16* Vs = smc + 2 * CTX_ELEM;
    uint32_t ks_base = (uint32_t)__cvta_generic_to_shared(Ks);
    uint32_t vs_base = (uint32_t)__cvta_generic_to_shared(Vs);

    int bh = blockIdx.y;
    int b = bh >> 2, h = bh & 3;
    int nbase = blockIdx.x * 1024;
    const bf16* kp = g_kb   + (size_t)b * CDIM * NPOS + (size_t)(h * CH) * NPOS + nbase;
    const bf16* vp = g_qkvb + (size_t)b * OC * NPOS + (size_t)(2 * CDIM + h * CH) * NPOS + nbase;

    int tid = threadIdx.x, lane = tid & 31, warp = tid >> 5;
    int wm = (warp >> 2) * 48, wn = (warp & 3) * 24;

    float acc[3][3][4];
#pragma unroll
    for (int i = 0; i < 3; i++)
#pragma unroll
        for (int j = 0; j < 3; j++)
#pragma unroll
            for (int r = 0; r < 4; r++) acc[i][j][r] = 0.f;

    CLOAD(0, 0)
    for (int it = 0; it < 16; it++) {
        if (it + 1 < 16) {
            CLOAD((it + 1) & 1, (it + 1) * 64)
            cp_wait<1>();
        } else {
            cp_wait<0>();
        }
        __syncthreads();

        const bf16* Kst = Ks + (it & 1) * CTX_ELEM;
        const bf16* Vst = Vs + (it & 1) * CTX_ELEM;
#pragma unroll
        for (int h16 = 0; h16 < 4; h16++) {
            int kk = h16 * 16 + (lane & 3) * 2;
            uint32_t a[3][4], bq[3][2];
#pragma unroll
            for (int mf = 0; mf < 3; mf++) {
                int r = wm + mf * 16 + (lane >> 2);
                a[mf][0] = *(const uint32_t*)&Kst[r * CTS + kk];
                a[mf][1] = *(const uint32_t*)&Kst[(r + 8) * CTS + kk];
                a[mf][2] = *(const uint32_t*)&Kst[r * CTS + kk + 8];
                a[mf][3] = *(const uint32_t*)&Kst[(r + 8) * CTS + kk + 8];
            }
#pragma unroll
            for (int nf = 0; nf < 3; nf++) {
                int e = wn + nf * 8 + (lane >> 2);
                bq[nf][0] = *(const uint32_t*)&Vst[e * CTS + kk];
                bq[nf][1] = *(const uint32_t*)&Vst[e * CTS + kk + 8];
            }
#pragma unroll
            for (int mf = 0; mf < 3; mf++)
#pragma unroll
                for (int nf = 0; nf < 3; nf++)
                    mma16(acc[mf][nf], a[mf], bq[nf]);
        }
        __syncthreads();
    }

    float* cx = g_ctx + (size_t)bh * CH * CH;
#pragma unroll
    for (int mf = 0; mf < 3; mf++) {
        int r0 = wm + mf * 16 + (lane >> 2);
#pragma unroll
        for (int nf = 0; nf < 3; nf++) {
            int cc = wn + nf * 8 + 2 * (lane & 3);
            atomicAdd(&cx[r0 * CH + cc],           acc[mf][nf][0]);
            atomicAdd(&cx[r0 * CH + cc + 1],       acc[mf][nf][1]);
            atomicAdd(&cx[(r0 + 8) * CH + cc],     acc[mf][nf][2]);
            atomicAdd(&cx[(r0 + 8) * CH + cc + 1], acc[mf][nf][3]);
        }
    }
}

// ------------- fold ctx into Wout -> W2 bf16
__global__ void w2_kernel(const float* __restrict__ Wout)
{
    __shared__ float sc[CH][CH + 1];
    int h = blockIdx.x & 3;
    int b = blockIdx.x >> 2;
    const float* cx = g_ctx + (size_t)(b * HEADS + h) * CH * CH;
    int t = threadIdx.x;
    for (int idx = t; idx < CH * CH; idx += 256)
        sc[idx / CH][idx % CH] = cx[idx];
    __syncthreads();
    for (int idx = t; idx < CDIM * CH; idx += 256) {
        int o = idx / CH, d = idx % CH;
        const float* wr = Wout + (size_t)o * CDIM + h * CH;
        float a = 0.f;
#pragma unroll 8
        for (int e = 0; e < CH; e++) a = fmaf(wr[e], sc[d][e], a);
        g_w2b[(size_t)b * CDIM * CDIM + (size_t)o * CDIM + h * CH + d] =
            __float2bfloat16_rn(a);
    }
}

// ------------------ output LN + recomputed residual -> d_out
__global__ void ln_out_kernel(const float* __restrict__ og,
                              const float* __restrict__ x,
                              const float* __restrict__ pg,
                              float* __restrict__ out)
{
    int n = blockIdx.x * blockDim.x + threadIdx.x;
    int b = blockIdx.y;
    const float* yp = g_out2 + (size_t)b * CDIM * NPOS + n;
    const float* xp = x      + (size_t)b * CDIM * NPOS + n;
    float2 st = g_stats[b * NPOS + n];
    float pmean = st.x, pinv = st.y;

    float s = 0.f, ss = 0.f;
#pragma unroll 8
    for (int c = 0; c < CDIM; c++) {
        float v = yp[(size_t)c * NPOS];
        s += v; ss += v * v;
    }
    float mean = s * (1.f / CDIM);
    float var  = ss * (1.f / CDIM) - mean * mean;
    float inv  = rsqrtf(var + 1e-5f);
    float* op = out + (size_t)b * CDIM * NPOS + n;
#pragma unroll 8
    for (int c = 0; c < CDIM; c++) {
        float xn = (xp[(size_t)c * NPOS] - pmean) * pinv * pg[c];
        op[(size_t)c * NPOS] = (yp[(size_t)c * NPOS] - mean) * inv * og[c] + xn;
    }
}

// ---------------------------------------------------------------------------
extern "C" void kernel_launch(void* const* d_in, const int* in_sizes, int n_in,
                              void* d_out, int out_size)
{
    const float* x         = (const float*)d_in[0];
    const float* prenorm_g = (const float*)d_in[1];
    const float* Wqkv      = (const float*)d_in[2];
    const float* Wout      = (const float*)d_in[3];
    const float* bout      = (const float*)d_in[4];
    const float* outnorm_g = (const float*)d_in[5];
    float* out = (float*)d_out;

    bf16 *p_wqkvb, *p_xnT, *p_qkvb, *p_kb, *p_qT, *p_w2b;
    float *p_ctx, *p_out2;
    cudaGetSymbolAddress((void**)&p_wqkvb, g_wqkvb);
    cudaGetSymbolAddress((void**)&p_xnT,   g_xnT);
    cudaGetSymbolAddress((void**)&p_qkvb,  g_qkvb);
    cudaGetSymbolAddress((void**)&p_kb,    g_kb);
    cudaGetSymbolAddress((void**)&p_qT,    g_qT);
    cudaGetSymbolAddress((void**)&p_w2b,   g_w2b);
    cudaGetSymbolAddress((void**)&p_ctx,   g_ctx);
    cudaGetSymbolAddress((void**)&p_out2,  g_out2);

    cudaFuncSetAttribute(mma_gemm_kernel<false, true>,
                         cudaFuncAttributeMaxDynamicSharedMemorySize, GEMM_SMEM);
    cudaFuncSetAttribute(mma_gemm_kernel<true, false>,
                         cudaFuncAttributeMaxDynamicSharedMemorySize, GEMM_SMEM);
    cudaFuncSetAttribute(context_kernel,
                         cudaFuncAttributeMaxDynamicSharedMemorySize, CTX_SMEM);
    cudaFuncSetAttribute(softmax_q_kernel,
                         cudaFuncAttributeMaxDynamicSharedMemorySize, SQ_SMEM);

    // 0. convert Wqkv
    conv_wqkv_kernel<<<(OC * CDIM + 255) / 256, 256>>>(Wqkv);

    // 1. prenorm stats + xnT bf16
    ln_pre_kernel<<<dim3(NPOS / 128, BATCH), 128>>>(x, prenorm_g);

    // 2. qkv = Wqkv @ xn  (M=1152, N=4096, K=384; bf16 out)
    mma_gemm_kernel<false, true><<<dim3(NPOS / 128, OC / 128, BATCH), 256, GEMM_SMEM>>>(
        p_wqkvb, 0LL,
        p_xnT,  (long long)NPOS * CDIM,
        p_qkvb, (long long)OC * NPOS,
        nullptr, OC, NPOS, CDIM);

    // 3. softmaxes
    softmax_q_kernel<<<dim3(NPOS / 128, HEADS, BATCH), 128, SQ_SMEM>>>();
    softmax_k_kernel<<<dim3(CDIM, BATCH), 256>>>();

    // 4. context (split-K=4)
    int ctx_elems = BATCH * HEADS * CH * CH;
    zero_kernel<<<(ctx_elems + 255) / 256, 256>>>(p_ctx, ctx_elems);
    context_kernel<<<dim3(4, BATCH * HEADS), 256, CTX_SMEM>>>();

    // 5. fold ctx into Wout -> W2 bf16
    w2_kernel<<<BATCH * HEADS, 256>>>(Wout);

    // 6. out2 = W2 @ q + bout  (M=384, N=4096, K=384; f32 out)
    mma_gemm_kernel<true, false><<<dim3(NPOS / 128, CDIM / 128, BATCH), 256, GEMM_SMEM>>>(
        p_w2b, (long long)CDIM * CDIM,
        p_qT,  (long long)NPOS * CDIM,
        p_out2,(long long)CDIM * NPOS,
        bout, CDIM, NPOS, CDIM);

    // 7. output LN + residual
    ln_out_kernel<<<dim3(NPOS / 128, BATCH), 128>>>(outnorm_g, x, prenorm_g, out);
}

// round 17
// speedup vs baseline: 3.8130x; 1.0746x over previous
#include <cuda_runtime.h>
#include <cuda_bf16.h>
#include <cstdint>

// ---------------------------------------------------------------------------
// LinearAttention (b=16, dim=384, n=4096, heads=4, ch=96) — bf16 tensor cores.
// R11: 3-stage single-sync GEMM pipeline; bf16-smem softmax_q (2x occ);
//      vectorized softmax_k.
// ---------------------------------------------------------------------------

typedef __nv_bfloat16 bf16;

#define BATCH 16
#define CDIM  384
#define NPOS  4096
#define HEADS 4
#define CH    96
#define OC    1152
#define QSCALE 0.1020620726159658f

static __device__ bf16   g_wqkvb[OC * CDIM];
static __device__ bf16   g_xnT [BATCH * NPOS * CDIM];        // [b][n][c]
static __device__ float2 g_stats[BATCH * NPOS];              // (mean, inv)
static __device__ bf16   g_qkvb[BATCH * OC * NPOS];          // [b][1152][n]
static __device__ bf16   g_kb  [BATCH * CDIM * NPOS];        // softmaxed k
static __device__ bf16   g_qT  [BATCH * NPOS * CDIM];        // softmaxed q, [n][c]
static __device__ float  g_ctx [BATCH * HEADS * CH * CH];
static __device__ bf16   g_w2b [BATCH * CDIM * CDIM];
static __device__ float  g_out2[BATCH * CDIM * NPOS];

// ------------------------------------------------------------- helpers
__device__ __forceinline__ void mma16(float* d, const uint32_t* a, const uint32_t* b) {
    asm volatile(
        "mma.sync.aligned.m16n8k16.row.col.f32.bf16.bf16.f32 "
        "{%0,%1,%2,%3}, {%4,%5,%6,%7}, {%8,%9}, {%0,%1,%2,%3};"
        : "+f"(d[0]), "+f"(d[1]), "+f"(d[2]), "+f"(d[3])
        : "r"(a[0]), "r"(a[1]), "r"(a[2]), "r"(a[3]), "r"(b[0]), "r"(b[1]));
}
__device__ __forceinline__ void cp_async16(uint32_t saddr, const void* g) {
    asm volatile("cp.async.ca.shared.global [%0], [%1], 16;" :: "r"(saddr), "l"(g));
}
__device__ __forceinline__ void cp_commit() { asm volatile("cp.async.commit_group;"); }
template<int N>
__device__ __forceinline__ void cp_wait() { asm volatile("cp.async.wait_group %0;" :: "n"(N)); }

// --------------------------------------------------- Wqkv f32 -> bf16
__global__ void conv_wqkv_kernel(const float* __restrict__ w)
{
    int i = blockIdx.x * blockDim.x + threadIdx.x;
    if (i < OC * CDIM) g_wqkvb[i] = __float2bfloat16_rn(w[i]);
}

// -------------------------------------- prenorm: stats + transposed bf16 xn
__global__ void ln_pre_kernel(const float* __restrict__ x,
                              const float* __restrict__ g)
{
    __shared__ float tile[32][129];
    int t = threadIdx.x;                 // 128
    int n0 = blockIdx.x * 128;
    int n = n0 + t;
    int b = blockIdx.y;
    const float* xp = x + (size_t)b * CDIM * NPOS + n;

    float s = 0.f, ss = 0.f;
#pragma unroll 8
    for (int c = 0; c < CDIM; c++) {
        float v = xp[(size_t)c * NPOS];
        s += v; ss += v * v;
    }
    float mean = s * (1.f / CDIM);
    float var  = ss * (1.f / CDIM) - mean * mean;
    float inv  = rsqrtf(var + 1e-5f);
    g_stats[b * NPOS + n] = make_float2(mean, inv);

    bf16* xnT = g_xnT + (size_t)b * NPOS * CDIM;
    for (int c0 = 0; c0 < CDIM; c0 += 32) {
#pragma unroll
        for (int i = 0; i < 32; i++)
            tile[i][t] = (xp[(size_t)(c0 + i) * NPOS] - mean) * inv * g[c0 + i];
        __syncthreads();
        for (int idx = t; idx < 128 * 16; idx += 128) {
            int rr = idx >> 4, pp = idx & 15;
            __nv_bfloat162 p = __floats2bfloat162_rn(tile[2 * pp][rr], tile[2 * pp + 1][rr]);
            *(__nv_bfloat162*)&xnT[(size_t)(n0 + rr) * CDIM + c0 + 2 * pp] = p;
        }
        __syncthreads();
    }
}

// -------------------- bf16 GEMM 128x128x32, 8 warps, 3-stage single-sync
// C = A[M][K] * B[N][K]^T ; A,B bf16 k-contiguous; C f32 (+bias) or bf16.
#define GAS    40                 // smem k-stride (bf16)
#define GM_ASZ (128 * GAS)        // per-stage elems per operand
#define GEMM_SMEM (6 * GM_ASZ * 2)   // 3 stages x 2 operands

#define GLOAD(s, k0)                                                            \
    {                                                                           \
        _Pragma("unroll")                                                       \
        for (int c = 0; c < 2; c++) {                                           \
            int chunk = tid + c * 256;                                          \
            int mm = chunk >> 2, kc = (chunk & 3) * 8;                          \
            cp_async16(as_base + (uint32_t)(((s) * GM_ASZ + mm * GAS + kc) * 2),\
                       Ab + (size_t)(m0 + mm) * K + (k0) + kc);                 \
            cp_async16(bs_base + (uint32_t)(((s) * GM_ASZ + mm * GAS + kc) * 2),\
                       Bb + (size_t)(n0 + mm) * K + (k0) + kc);                 \
        }                                                                       \
        cp_commit();                                                            \
    }

template<bool BIAS, bool OUTBF>
__global__ __launch_bounds__(256, 2)
void mma_gemm_kernel(const bf16* __restrict__ A, long long sA,
                     const bf16* __restrict__ B, long long sB,
                     void* __restrict__ Cv, long long sC,
                     const float* __restrict__ bias,
                     int M, int N, int K)
{
    extern __shared__ bf16 smb[];
    bf16* As = smb;
    bf16* Bs = smb + 3 * GM_ASZ;
    uint32_t as_base = (uint32_t)__cvta_generic_to_shared(As);
    uint32_t bs_base = (uint32_t)__cvta_generic_to_shared(Bs);

    int bz = blockIdx.z;
    const bf16* Ab = A + sA * bz;
    const bf16* Bb = B + sB * bz;
    int m0 = blockIdx.y * 128, n0 = blockIdx.x * 128;
    int tid = threadIdx.x, lane = tid & 31, warp = tid >> 5;
    int wm = (warp >> 2) * 64, wn = (warp & 3) * 32;

    float acc[4][4][4];
#pragma unroll
    for (int i = 0; i < 4; i++)
#pragma unroll
        for (int j = 0; j < 4; j++)
#pragma unroll
            for (int r = 0; r < 4; r++) acc[i][j][r] = 0.f;

    int nIter = K / 32;                  // 12
    GLOAD(0, 0)
    GLOAD(1, 32)

    for (int it = 0; it < nIter; it++) {
        if (it + 1 < nIter) { cp_wait<1>(); } else { cp_wait<0>(); }
        __syncthreads();                 // single barrier per iteration

        int st = it % 3;
        const bf16* Ast = As + st * GM_ASZ;
        const bf16* Bst = Bs + st * GM_ASZ;
#pragma unroll
        for (int h16 = 0; h16 < 2; h16++) {
            int kk = h16 * 16 + (lane & 3) * 2;
            uint32_t a[4][4], bq[4][2];
#pragma unroll
            for (int mf = 0; mf < 4; mf++) {
                int r = wm + mf * 16 + (lane >> 2);
                a[mf][0] = *(const uint32_t*)&Ast[r * GAS + kk];
                a[mf][1] = *(const uint32_t*)&Ast[(r + 8) * GAS + kk];
                a[mf][2] = *(const uint32_t*)&Ast[r * GAS + kk + 8];
                a[mf][3] = *(const uint32_t*)&Ast[(r + 8) * GAS + kk + 8];
            }
#pragma unroll
            for (int nf = 0; nf < 4; nf++) {
                int nn = wn + nf * 8 + (lane >> 2);
                bq[nf][0] = *(const uint32_t*)&Bst[nn * GAS + kk];
                bq[nf][1] = *(const uint32_t*)&Bst[nn * GAS + kk + 8];
            }
#pragma unroll
            for (int mf = 0; mf < 4; mf++)
#pragma unroll
                for (int nf = 0; nf < 4; nf++)
                    mma16(acc[mf][nf], a[mf], bq[nf]);
        }
        // stage (it+2)%3 was fully consumed at iter it-1; the barrier above
        // guarantees every warp has passed that point -> safe to overwrite.
        if (it + 2 < nIter) { GLOAD((it + 2) % 3, (it + 2) * 32) }
    }

    if (OUTBF) {
        bf16* Cb = (bf16*)Cv + (size_t)sC * bz;
#pragma unroll
        for (int mf = 0; mf < 4; mf++) {
            int r0 = m0 + wm + mf * 16 + (lane >> 2);
#pragma unroll
            for (int nf = 0; nf < 4; nf++) {
                int cc = n0 + wn + nf * 8 + 2 * (lane & 3);
                *(__nv_bfloat162*)&Cb[(size_t)r0 * N + cc] =
                    __floats2bfloat162_rn(acc[mf][nf][0], acc[mf][nf][1]);
                *(__nv_bfloat162*)&Cb[(size_t)(r0 + 8) * N + cc] =
                    __floats2bfloat162_rn(acc[mf][nf][2], acc[mf][nf][3]);
            }
        }
    } else {
        float* Cb = (float*)Cv + (size_t)sC * bz;
#pragma unroll
        for (int mf = 0; mf < 4; mf++) {
            int r0 = m0 + wm + mf * 16 + (lane >> 2);
            float bi0 = BIAS ? bias[r0] : 0.f;
            float bi1 = BIAS ? bias[r0 + 8] : 0.f;
#pragma unroll
            for (int nf = 0; nf < 4; nf++) {
                int cc = n0 + wn + nf * 8 + 2 * (lane & 3);
                *(float2*)&Cb[(size_t)r0 * N + cc] =
                    make_float2(acc[mf][nf][0] + bi0, acc[mf][nf][1] + bi0);
                *(float2*)&Cb[(size_t)(r0 + 8) * N + cc] =
                    make_float2(acc[mf][nf][2] + bi1, acc[mf][nf][3] + bi1);
            }
        }
    }
}

// ----------- q softmax over 96 ch, *scale; bf16 smem (2x occupancy)
#define SQB_STRIDE 130
#define SQ_SMEM (CH * SQB_STRIDE * 2)      // 24,960 B
__global__ void softmax_q_kernel()
{
    extern __shared__ bf16 sqb[];          // [96][130] bf16
    __shared__ float rbuf[128];
    int n0 = blockIdx.x * 128;
    int h  = blockIdx.y;
    int b  = blockIdx.z;
    int t  = threadIdx.x;
    const bf16* qp = g_qkvb + (size_t)b * OC * NPOS + (size_t)(h * CH) * NPOS + n0 + t;

#pragma unroll 4
    for (int d = 0; d < CH; d++)
        sqb[d * SQB_STRIDE + t] = qp[(size_t)d * NPOS];        // lossless copy
    float mx = -1e30f;
#pragma unroll 4
    for (int d = 0; d < CH; d++)
        mx = fmaxf(mx, __bfloat162float(sqb[d * SQB_STRIDE + t]));
    float s = 0.f;
#pragma unroll 4
    for (int d = 0; d < CH; d++) {
        float e = __expf(__bfloat162float(sqb[d * SQB_STRIDE + t]) - mx);
        s += e;
        sqb[d * SQB_STRIDE + t] = __float2bfloat16_rn(e);
    }
    rbuf[t] = QSCALE / s;
    __syncthreads();

    bf16* qT = g_qT + (size_t)b * NPOS * CDIM;
    for (int idx = t; idx < 128 * (CH / 2); idx += 128) {
        int rr = idx / (CH / 2), pp = idx - rr * (CH / 2);
        float r = rbuf[rr];
        __nv_bfloat162 p = __floats2bfloat162_rn(
            __bfloat162float(sqb[(2 * pp)     * SQB_STRIDE + rr]) * r,
            __bfloat162float(sqb[(2 * pp + 1) * SQB_STRIDE + rr]) * r);
        *(__nv_bfloat162*)&qT[(size_t)(n0 + rr) * CDIM + h * CH + 2 * pp] = p;
    }
}

// -------------------------------------- k softmax over n=4096; vectorized
__device__ __forceinline__ float block_reduce(float v, bool is_max)
{
    __shared__ float sred[32];
#pragma unroll
    for (int o = 16; o; o >>= 1) {
        float u = __shfl_xor_sync(0xffffffff, v, o);
        v = is_max ? fmaxf(v, u) : v + u;
    }
    int w = threadIdx.x >> 5;
    __syncthreads();
    if ((threadIdx.x & 31) == 0) sred[w] = v;
    __syncthreads();
    if (w == 0) {
        int nw = blockDim.x >> 5;
        v = (threadIdx.x < nw) ? sred[threadIdx.x] : (is_max ? -1e30f : 0.f);
#pragma unroll
        for (int o = 16; o; o >>= 1) {
            float u = __shfl_xor_sync(0xffffffff, v, o);
            v = is_max ? fmaxf(v, u) : v + u;
        }
        if (threadIdx.x == 0) sred[0] = v;
    }
    __syncthreads();
    return sred[0];
}

__global__ void softmax_k_kernel()
{
    __shared__ float row[NPOS];
    int c = blockIdx.x;
    int b = blockIdx.y;
    const __nv_bfloat162* kin2 = (const __nv_bfloat162*)
        (g_qkvb + (size_t)b * OC * NPOS + (size_t)(CDIM + c) * NPOS);
    __nv_bfloat162* kout2 = (__nv_bfloat162*)
        (g_kb + (size_t)b * CDIM * NPOS + (size_t)c * NPOS);
    int t = threadIdx.x;
    float mx = -1e30f;
    for (int i = t; i < NPOS / 2; i += 256) {
        float2 v = __bfloat1622float2(kin2[i]);
        *(float2*)&row[2 * i] = v;
        mx = fmaxf(mx, fmaxf(v.x, v.y));
    }
    mx = block_reduce(mx, true);
    float s = 0.f;
    for (int i = t; i < NPOS; i += 256) {
        float e = __expf(row[i] - mx);
        row[i] = e; s += e;
    }
    s = block_reduce(s, false);
    float r = 1.f / s;
    for (int i = t; i < NPOS / 2; i += 256)
        kout2[i] = __floats2bfloat162_rn(row[2 * i] * r, row[2 * i + 1] * r);
}

// ---------------------------------------------------------------- zero scratch
__global__ void zero_kernel(float* p, int n)
{
    int i = blockIdx.x * blockDim.x + threadIdx.x;
    if (i < n) p[i] = 0.f;
}

// ------------- context (bf16 mma): ctx[d,e] = sum_n k[d,n] v[e,n]; split-K=4
#define CTS      72               // smem k-stride (bf16), K-tile 64
#define CTX_ELEM (96 * CTS)
#define CTX_SMEM (4 * CTX_ELEM * 2)

#define CLOAD(s, kk0)                                                           \
    {                                                                           \
        _Pragma("unroll")                                                       \
        for (int c = 0; c < 3; c++) {                                           \
            int chunk = tid + c * 256;                                          \
            int rr = chunk >> 3, kc = (chunk & 7) * 8;                          \
            cp_async16(ks_base + (uint32_t)(((s) * CTX_ELEM + rr * CTS + kc) * 2),\
                       kp + (size_t)rr * NPOS + (kk0) + kc);                    \
            cp_async16(vs_base + (uint32_t)(((s) * CTX_ELEM + rr * CTS + kc) * 2),\
                       vp + (size_t)rr * NPOS + (kk0) + kc);                    \
        }                                                                       \
        cp_commit();                                                            \
    }

__global__ __launch_bounds__(256, 2)
void context_kernel()
{
    extern __shared__ bf16 smc[];
    bf16* Ks = smc;
    bf16* Vs = smc + 2 * CTX_ELEM;
    uint32_t ks_base = (uint32_t)__cvta_generic_to_shared(Ks);
    uint32_t vs_base = (uint32_t)__cvta_generic_to_shared(Vs);

    int bh = blockIdx.y;
    int b = bh >> 2, h = bh & 3;
    int nbase = blockIdx.x * 1024;
    const bf16* kp = g_kb   + (size_t)b * CDIM * NPOS + (size_t)(h * CH) * NPOS + nbase;
    const bf16* vp = g_qkvb + (size_t)b * OC * NPOS + (size_t)(2 * CDIM + h * CH) * NPOS + nbase;

    int tid = threadIdx.x, lane = tid & 31, warp = tid >> 5;
    int wm = (warp >> 2) * 48, wn = (warp & 3) * 24;

    float acc[3][3][4];
#pragma unroll
    for (int i = 0; i < 3; i++)
#pragma unroll
        for (int j = 0; j < 3; j++)
#pragma unroll
            for (int r = 0; r < 4; r++) acc[i][j][r] = 0.f;

    CLOAD(0, 0)
    for (int it = 0; it < 16; it++) {
        if (it + 1 < 16) {
            CLOAD((it + 1) & 1, (it + 1) * 64)
            cp_wait<1>();
        } else {
            cp_wait<0>();
        }
        __syncthreads();

        const bf16* Kst = Ks + (it & 1) * CTX_ELEM;
        const bf16* Vst = Vs + (it & 1) * CTX_ELEM;
#pragma unroll
        for (int h16 = 0; h16 < 4; h16++) {
            int kk = h16 * 16 + (lane & 3) * 2;
            uint32_t a[3][4], bq[3][2];
#pragma unroll
            for (int mf = 0; mf < 3; mf++) {
                int r = wm + mf * 16 + (lane >> 2);
                a[mf][0] = *(const uint32_t*)&Kst[r * CTS + kk];
                a[mf][1] = *(const uint32_t*)&Kst[(r + 8) * CTS + kk];
                a[mf][2] = *(const uint32_t*)&Kst[r * CTS + kk + 8];
                a[mf][3] = *(const uint32_t*)&Kst[(r + 8) * CTS + kk + 8];
            }
#pragma unroll
            for (int nf = 0; nf < 3; nf++) {
                int e = wn + nf * 8 + (lane >> 2);
                bq[nf][0] = *(const uint32_t*)&Vst[e * CTS + kk];
                bq[nf][1] = *(const uint32_t*)&Vst[e * CTS + kk + 8];
            }
#pragma unroll
            for (int mf = 0; mf < 3; mf++)
#pragma unroll
                for (int nf = 0; nf < 3; nf++)
                    mma16(acc[mf][nf], a[mf], bq[nf]);
        }
        __syncthreads();
    }

    float* cx = g_ctx + (size_t)bh * CH * CH;
#pragma unroll
    for (int mf = 0; mf < 3; mf++) {
        int r0 = wm + mf * 16 + (lane >> 2);
#pragma unroll
        for (int nf = 0; nf < 3; nf++) {
            int cc = wn + nf * 8 + 2 * (lane & 3);
            atomicAdd(&cx[r0 * CH + cc],           acc[mf][nf][0]);
            atomicAdd(&cx[r0 * CH + cc + 1],       acc[mf][nf][1]);
            atomicAdd(&cx[(r0 + 8) * CH + cc],     acc[mf][nf][2]);
            atomicAdd(&cx[(r0 + 8) * CH + cc + 1], acc[mf][nf][3]);
        }
    }
}

// ------------- fold ctx into Wout -> W2 bf16
__global__ void w2_kernel(const float* __restrict__ Wout)
{
    __shared__ float sc[CH][CH + 1];
    int h = blockIdx.x & 3;
    int b = blockIdx.x >> 2;
    const float* cx = g_ctx + (size_t)(b * HEADS + h) * CH * CH;
    int t = threadIdx.x;
    for (int idx = t; idx < CH * CH; idx += 256)
        sc[idx / CH][idx % CH] = cx[idx];
    __syncthreads();
    for (int idx = t; idx < CDIM * CH; idx += 256) {
        int o = idx / CH, d = idx % CH;
        const float* wr = Wout + (size_t)o * CDIM + h * CH;
        float a = 0.f;
#pragma unroll 8
        for (int e = 0; e < CH; e++) a = fmaf(wr[e], sc[d][e], a);
        g_w2b[(size_t)b * CDIM * CDIM + (size_t)o * CDIM + h * CH + d] =
            __float2bfloat16_rn(a);
    }
}

// ------------------ output LN + recomputed residual -> d_out
__global__ void ln_out_kernel(const float* __restrict__ og,
                              const float* __restrict__ x,
                              const float* __restrict__ pg,
                              float* __restrict__ out)
{
    int n = blockIdx.x * blockDim.x + threadIdx.x;
    int b = blockIdx.y;
    const float* yp = g_out2 + (size_t)b * CDIM * NPOS + n;
    const float* xp = x      + (size_t)b * CDIM * NPOS + n;
    float2 st = g_stats[b * NPOS + n];
    float pmean = st.x, pinv = st.y;

    float s = 0.f, ss = 0.f;
#pragma unroll 8
    for (int c = 0; c < CDIM; c++) {
        float v = yp[(size_t)c * NPOS];
        s += v; ss += v * v;
    }
    float mean = s * (1.f / CDIM);
    float var  = ss * (1.f / CDIM) - mean * mean;
    float inv  = rsqrtf(var + 1e-5f);
    float* op = out + (size_t)b * CDIM * NPOS + n;
#pragma unroll 8
    for (int c = 0; c < CDIM; c++) {
        float xn = (xp[(size_t)c * NPOS] - pmean) * pinv * pg[c];
        op[(size_t)c * NPOS] = (yp[(size_t)c * NPOS] - mean) * inv * og[c] + xn;
    }
}

// ---------------------------------------------------------------------------
extern "C" void kernel_launch(void* const* d_in, const int* in_sizes, int n_in,
                              void* d_out, int out_size)
{
    const float* x         = (const float*)d_in[0];
    const float* prenorm_g = (const float*)d_in[1];
    const float* Wqkv      = (const float*)d_in[2];
    const float* Wout      = (const float*)d_in[3];
    const float* bout      = (const float*)d_in[4];
    const float* outnorm_g = (const float*)d_in[5];
    float* out = (float*)d_out;

    bf16 *p_wqkvb, *p_xnT, *p_qkvb, *p_kb, *p_qT, *p_w2b;
    float *p_ctx, *p_out2;
    cudaGetSymbolAddress((void**)&p_wqkvb, g_wqkvb);
    cudaGetSymbolAddress((void**)&p_xnT,   g_xnT);
    cudaGetSymbolAddress((void**)&p_qkvb,  g_qkvb);
    cudaGetSymbolAddress((void**)&p_kb,    g_kb);
    cudaGetSymbolAddress((void**)&p_qT,    g_qT);
    cudaGetSymbolAddress((void**)&p_w2b,   g_w2b);
    cudaGetSymbolAddress((void**)&p_ctx,   g_ctx);
    cudaGetSymbolAddress((void**)&p_out2,  g_out2);

    cudaFuncSetAttribute(mma_gemm_kernel<false, true>,
                         cudaFuncAttributeMaxDynamicSharedMemorySize, GEMM_SMEM);
    cudaFuncSetAttribute(mma_gemm_kernel<true, false>,
                         cudaFuncAttributeMaxDynamicSharedMemorySize, GEMM_SMEM);
    cudaFuncSetAttribute(context_kernel,
                         cudaFuncAttributeMaxDynamicSharedMemorySize, CTX_SMEM);
    cudaFuncSetAttribute(softmax_q_kernel,
                         cudaFuncAttributeMaxDynamicSharedMemorySize, SQ_SMEM);

    // 0. convert Wqkv
    conv_wqkv_kernel<<<(OC * CDIM + 255) / 256, 256>>>(Wqkv);

    // 1. prenorm stats + xnT bf16
    ln_pre_kernel<<<dim3(NPOS / 128, BATCH), 128>>>(x, prenorm_g);

    // 2. qkv = Wqkv @ xn  (M=1152, N=4096, K=384; bf16 out)
    mma_gemm_kernel<false, true><<<dim3(NPOS / 128, OC / 128, BATCH), 256, GEMM_SMEM>>>(
        p_wqkvb, 0LL,
        p_xnT,  (long long)NPOS * CDIM,
        p_qkvb, (long long)OC * NPOS,
        nullptr, OC, NPOS, CDIM);

    // 3. softmaxes
    softmax_q_kernel<<<dim3(NPOS / 128, HEADS, BATCH), 128, SQ_SMEM>>>();
    softmax_k_kernel<<<dim3(CDIM, BATCH), 256>>>();

    // 4. context (split-K=4)
    int ctx_elems = BATCH * HEADS * CH * CH;
    zero_kernel<<<(ctx_elems + 255) / 256, 256>>>(p_ctx, ctx_elems);
    context_kernel<<<dim3(4, BATCH * HEADS), 256, CTX_SMEM>>>();

    // 5. fold ctx into Wout -> W2 bf16
    w2_kernel<<<BATCH * HEADS, 256>>>(Wout);

    // 6. out2 = W2 @ q + bout  (M=384, N=4096, K=384; f32 out)
    mma_gemm_kernel<true, false><<<dim3(NPOS / 128, CDIM / 128, BATCH), 256, GEMM_SMEM>>>(
        p_w2b, (long long)CDIM * CDIM,
        p_qT,  (long long)NPOS * CDIM,
        p_out2,(long long)CDIM * NPOS,
        bout, CDIM, NPOS, CDIM);

    // 7. output LN + residual
    ln_out_kernel<<<dim3(NPOS / 128, BATCH), 128>>>(outnorm_g, x, prenorm_g, out);
}